// round 5
// baseline (speedup 1.0000x reference)
#include <cuda_runtime.h>
#include <math.h>
#include <float.h>

#define NN 100000
#define EE 1600000
#define HH 64
#define CC 10
#define SCAN_BLK 1024
#define SCAN_NBLK ((NN + SCAN_BLK - 1) / SCAN_BLK)   // 98

// ---------------- static device scratch ----------------
__device__ int   g_dst[EE];
__device__ int   g_col[EE];
__device__ int   g_deg[NN];
__device__ int   g_rowptr[NN + 1];
__device__ int   g_cursor[NN];
__device__ int   g_blocksum[SCAN_NBLK];
__device__ float g_h[NN * HH];
__device__ float g_h2[NN * HH];
__device__ int   g_odd_nonzero;

// ---------------- setup: zero degrees + edge dtype detection ----------------
// int64 edge ids < 2^31 -> every odd 32-bit word is 0.
__global__ void zerodetect_kernel(const unsigned int* __restrict__ w) {
    int i = blockIdx.x * blockDim.x + threadIdx.x;
    if (i < NN) g_deg[i] = 0;
    if (i == 0) g_odd_nonzero = 0;
    if (i < 65536) {
        unsigned int v = w[2 * i + 1];
        if (v) atomicOr(&g_odd_nonzero, 1);
    }
}

__global__ void convert_kernel(const void* __restrict__ ei) {
    int i = blockIdx.x * blockDim.x + threadIdx.x;
    if (i >= EE) return;
    int d;
    if (g_odd_nonzero == 0) d = (int)((const long long*)ei)[EE + i];
    else                    d = ((const int*)ei)[EE + i];
    g_dst[i] = d;
    atomicAdd(&g_deg[d], 1);
}

// ---------------- multi-block exclusive scan ----------------
__global__ void scan_phase1() {
    __shared__ int warp_sums[32];
    int tid = threadIdx.x;
    int i = blockIdx.x * SCAN_BLK + tid;
    int v = (i < NN) ? g_deg[i] : 0;
    int lane = tid & 31, wid = tid >> 5;

    int incl = v;
#pragma unroll
    for (int off = 1; off < 32; off <<= 1) {
        int t = __shfl_up_sync(0xffffffffu, incl, off);
        if (lane >= off) incl += t;
    }
    if (lane == 31) warp_sums[wid] = incl;
    __syncthreads();
    if (wid == 0) {
        int ws = warp_sums[lane];
        int wincl = ws;
#pragma unroll
        for (int off = 1; off < 32; off <<= 1) {
            int t = __shfl_up_sync(0xffffffffu, wincl, off);
            if (lane >= off) wincl += t;
        }
        warp_sums[lane] = wincl - ws;
        if (lane == 31) g_blocksum[blockIdx.x] = wincl;
    }
    __syncthreads();
    int excl = incl - v + warp_sums[wid];
    if (i < NN) g_rowptr[i] = excl;
}

__global__ void scan_phase2() {
    __shared__ int ws4[4];
    __shared__ int total;
    int tid = threadIdx.x;            // 128 threads
    int v = (tid < SCAN_NBLK) ? g_blocksum[tid] : 0;
    int lane = tid & 31, wid = tid >> 5;
    int incl = v;
#pragma unroll
    for (int off = 1; off < 32; off <<= 1) {
        int t = __shfl_up_sync(0xffffffffu, incl, off);
        if (lane >= off) incl += t;
    }
    if (lane == 31) ws4[wid] = incl;
    __syncthreads();
    if (tid == 0) {
        int c = 0;
        for (int w = 0; w < 4; w++) { int t = ws4[w]; ws4[w] = c; c += t; }
        total = c;
    }
    __syncthreads();
    if (tid < SCAN_NBLK) g_blocksum[tid] = incl - v + ws4[wid];
    if (tid == 0) g_rowptr[NN] = total;
}

__global__ void scan_phase3() {
    int i = blockIdx.x * SCAN_BLK + threadIdx.x;
    if (i >= NN) return;
    int r = g_rowptr[i] + g_blocksum[blockIdx.x];
    g_rowptr[i] = r;
    g_cursor[i] = r;
}

__global__ void scatter_kernel(const void* __restrict__ ei) {
    int i = blockIdx.x * blockDim.x + threadIdx.x;
    if (i >= EE) return;
    int s;
    if (g_odd_nonzero == 0) s = (int)((const long long*)ei)[i];
    else                    s = ((const int*)ei)[i];
    int d = g_dst[i];
    int pos = atomicAdd(&g_cursor[d], 1);
    g_col[pos] = s;
}

// ---------------- plain 64x64 GEMM (encoder): C = A @ W + b ----------------
__global__ void gemm64_kernel(const float* __restrict__ A,
                              const float* __restrict__ W,
                              const float* __restrict__ bias,
                              float* __restrict__ Cm, int n) {
    __shared__ float As[64][68];
    __shared__ float Ws[64][68];
    int tid = threadIdx.x;
    int block_row = blockIdx.x * 64;

    for (int i = tid; i < 1024; i += 256) {
        int k = i >> 4, j4 = i & 15;
        float4 v = ((const float4*)W)[i];
        *(float4*)&Ws[k][j4 * 4] = v;
    }
    for (int i = tid; i < 1024; i += 256) {
        int m = i >> 4, k4 = i & 15;
        int row = block_row + m;
        float4 v = make_float4(0.f, 0.f, 0.f, 0.f);
        if (row < n) v = ((const float4*)A)[row * 16 + k4];
        *(float4*)&As[m][k4 * 4] = v;
    }
    __syncthreads();

    int tx = tid & 15, ty = tid >> 4;
    int m0 = ty * 4, j0 = tx * 4;
    float acc[4][4];
#pragma unroll
    for (int i = 0; i < 4; i++)
#pragma unroll
        for (int j = 0; j < 4; j++) acc[i][j] = 0.f;

#pragma unroll 16
    for (int k = 0; k < 64; k++) {
        float b0 = Ws[k][j0], b1 = Ws[k][j0 + 1], b2 = Ws[k][j0 + 2], b3 = Ws[k][j0 + 3];
#pragma unroll
        for (int i = 0; i < 4; i++) {
            float a = As[m0 + i][k];
            acc[i][0] = fmaf(a, b0, acc[i][0]);
            acc[i][1] = fmaf(a, b1, acc[i][1]);
            acc[i][2] = fmaf(a, b2, acc[i][2]);
            acc[i][3] = fmaf(a, b3, acc[i][3]);
        }
    }
    float bb0 = bias[j0], bb1 = bias[j0 + 1], bb2 = bias[j0 + 2], bb3 = bias[j0 + 3];
#pragma unroll
    for (int i = 0; i < 4; i++) {
        int row = block_row + m0 + i;
        if (row < n) {
            float4 o = make_float4(acc[i][0] + bb0, acc[i][1] + bb1,
                                   acc[i][2] + bb2, acc[i][3] + bb3);
            ((float4*)Cm)[row * 16 + (j0 >> 2)] = o;
        }
    }
}

// ---------------- fused GIN layer: segmax + add + GEMM ----------------
// h_next = (h_cur + segmax_neighbors(h_cur)) @ W + b
// Block = 64 nodes, 256 threads (8 warps x 8 nodes each). Double-buffered h,
// so gathers from h_cur are race-free while h_next is written. No agg buffer.
__global__ void gin_layer_kernel(const float* __restrict__ Hc,
                                 const float* __restrict__ W,
                                 const float* __restrict__ bias,
                                 float* __restrict__ Hn, int n) {
    __shared__ float As[64][68];
    __shared__ float Ws[64][68];
    int tid = threadIdx.x;
    int lane = tid & 31, wid = tid >> 5;
    int block_row = blockIdx.x * 64;

    // stage W
    for (int i = tid; i < 1024; i += 256) {
        int k = i >> 4, j4 = i & 15;
        float4 v = ((const float4*)W)[i];
        *(float4*)&Ws[k][j4 * 4] = v;
    }

    // Phase A: per-warp segmax + self-add, 8 nodes per warp
#pragma unroll 1
    for (int r = 0; r < 8; r++) {
        int m = wid * 8 + r;
        int node = block_row + m;
        if (node < n) {
            int beg = g_rowptr[node], end = g_rowptr[node + 1];
            float m0 = -FLT_MAX, m1 = -FLT_MAX;
            for (int base = beg; base < end; base += 32) {
                int cnt = min(32, end - base);
                int s = 0;
                if (lane < cnt) s = g_col[base + lane];
                for (int e = 0; e < cnt; e++) {
                    int sv = __shfl_sync(0xffffffffu, s, e);
                    float2 v = *(const float2*)(Hc + sv * HH + lane * 2);
                    m0 = fmaxf(m0, v.x);
                    m1 = fmaxf(m1, v.y);
                }
            }
            if (beg == end) { m0 = 0.f; m1 = 0.f; }
            float2 self = *(const float2*)(Hc + node * HH + lane * 2);
            As[m][lane * 2 + 0] = self.x + m0;
            As[m][lane * 2 + 1] = self.y + m1;
        }
    }
    __syncthreads();

    // Phase B: 64x64 GEMM on As
    int tx = tid & 15, ty = tid >> 4;
    int m0r = ty * 4, j0 = tx * 4;
    float acc[4][4];
#pragma unroll
    for (int i = 0; i < 4; i++)
#pragma unroll
        for (int j = 0; j < 4; j++) acc[i][j] = 0.f;

#pragma unroll 16
    for (int k = 0; k < 64; k++) {
        float b0 = Ws[k][j0], b1 = Ws[k][j0 + 1], b2 = Ws[k][j0 + 2], b3 = Ws[k][j0 + 3];
#pragma unroll
        for (int i = 0; i < 4; i++) {
            float a = As[m0r + i][k];
            acc[i][0] = fmaf(a, b0, acc[i][0]);
            acc[i][1] = fmaf(a, b1, acc[i][1]);
            acc[i][2] = fmaf(a, b2, acc[i][2]);
            acc[i][3] = fmaf(a, b3, acc[i][3]);
        }
    }
    float bb0 = bias[j0], bb1 = bias[j0 + 1], bb2 = bias[j0 + 2], bb3 = bias[j0 + 3];
#pragma unroll
    for (int i = 0; i < 4; i++) {
        int row = block_row + m0r + i;
        if (row < n) {
            float4 o = make_float4(acc[i][0] + bb0, acc[i][1] + bb1,
                                   acc[i][2] + bb2, acc[i][3] + bb3);
            ((float4*)Hn)[row * 16 + (j0 >> 2)] = o;
        }
    }
}

// ---------------- decoder + log-softmax ----------------
__global__ void decoder_kernel(const float* __restrict__ H,
                               const float* __restrict__ dw,
                               const float* __restrict__ db,
                               float* __restrict__ out, int n) {
    __shared__ float Ws[HH * CC];
    __shared__ float bs[CC];
    int tid = threadIdx.x;
    for (int i = tid; i < HH * CC; i += blockDim.x) Ws[i] = dw[i];
    if (tid < CC) bs[tid] = db[tid];
    __syncthreads();
    int node = blockIdx.x * blockDim.x + tid;
    if (node >= n) return;
    float acc[CC];
#pragma unroll
    for (int c = 0; c < CC; c++) acc[c] = bs[c];
    const float4* hp = (const float4*)(H + node * HH);
#pragma unroll
    for (int k4 = 0; k4 < 16; k4++) {
        float4 v = hp[k4];
        int kb = k4 * 4;
#pragma unroll
        for (int c = 0; c < CC; c++)
            acc[c] += v.x * Ws[(kb + 0) * CC + c] + v.y * Ws[(kb + 1) * CC + c] +
                      v.z * Ws[(kb + 2) * CC + c] + v.w * Ws[(kb + 3) * CC + c];
    }
    float mx = acc[0];
#pragma unroll
    for (int c = 1; c < CC; c++) mx = fmaxf(mx, acc[c]);
    float s = 0.f;
#pragma unroll
    for (int c = 0; c < CC; c++) s += expf(acc[c] - mx);
    float lse = mx + logf(s);
#pragma unroll
    for (int c = 0; c < CC; c++) out[node * CC + c] = acc[c] - lse;
}

// ---------------- launch ----------------
extern "C" void kernel_launch(void* const* d_in, const int* in_sizes, int n_in,
                              void* d_out, int out_size) {
    const float* x      = (const float*)d_in[0];
    const void*  ei     = d_in[1];
    const float* enc_w  = (const float*)d_in[3];
    const float* enc_b  = (const float*)d_in[4];
    const float* proc_w = (const float*)d_in[5];
    const float* proc_b = (const float*)d_in[6];
    const float* dec_w  = (const float*)d_in[7];
    const float* dec_b  = (const float*)d_in[8];
    float* out = (float*)d_out;

    float* h0 = nullptr;
    float* h1 = nullptr;
    cudaGetSymbolAddress((void**)&h0, g_h);
    cudaGetSymbolAddress((void**)&h1, g_h2);

    const int n = NN;

    // CSR build
    zerodetect_kernel<<<(NN + 255) / 256, 256>>>((const unsigned int*)ei);
    convert_kernel<<<(EE + 255) / 256, 256>>>(ei);
    scan_phase1<<<SCAN_NBLK, SCAN_BLK>>>();
    scan_phase2<<<1, 128>>>();
    scan_phase3<<<SCAN_NBLK, SCAN_BLK>>>();
    scatter_kernel<<<(EE + 255) / 256, 256>>>(ei);

    // encoder
    gemm64_kernel<<<(n + 63) / 64, 256>>>(x, enc_w, enc_b, h0, n);

    // 6 fused GIN layers, ping-pong buffers (even count -> ends in h0)
    float* cur = h0;
    float* nxt = h1;
    for (int it = 0; it < 6; it++) {
        gin_layer_kernel<<<(n + 63) / 64, 256>>>(cur, proc_w, proc_b, nxt, n);
        float* t = cur; cur = nxt; nxt = t;
    }

    // decoder + log-softmax
    decoder_kernel<<<(n + 127) / 128, 128>>>(cur, dec_w, dec_b, out, n);
}

// round 6
// speedup vs baseline: 1.1777x; 1.1777x over previous
#include <cuda_runtime.h>
#include <cuda_fp16.h>
#include <math.h>
#include <float.h>

#define NN 100000
#define EE 1600000
#define HH 64
#define CC 10
#define SCAN_BLK 1024
#define SCAN_NBLK ((NN + SCAN_BLK - 1) / SCAN_BLK)   // 98

// ---------------- static device scratch ----------------
__device__ int          g_dst[EE];
__device__ int          g_col[EE];
__device__ int          g_deg[NN];
__device__ int          g_rowptr[NN + 1];
__device__ int          g_cursor[NN];
__device__ int          g_blocksum[SCAN_NBLK];
__device__ float        g_h[NN * HH];        // fp32 node features
__device__ unsigned int g_hh[NN * 32];       // fp16x2 shadow copy (half2 per pair)
__device__ float        g_agg[NN * HH];      // segment-max result (fp32)
__device__ int          g_odd_nonzero;

// ---------------- setup: zero degrees + edge dtype detection ----------------
// int64 edge ids < 2^31 -> every odd 32-bit word is 0.
__global__ void zerodetect_kernel(const unsigned int* __restrict__ w) {
    int i = blockIdx.x * blockDim.x + threadIdx.x;
    if (i < NN) g_deg[i] = 0;
    if (i == 0) g_odd_nonzero = 0;
    if (i < 65536) {
        unsigned int v = w[2 * i + 1];
        if (v) atomicOr(&g_odd_nonzero, 1);
    }
}

__global__ void convert_kernel(const void* __restrict__ ei) {
    int i = blockIdx.x * blockDim.x + threadIdx.x;
    if (i >= EE) return;
    int d;
    if (g_odd_nonzero == 0) d = (int)((const long long*)ei)[EE + i];
    else                    d = ((const int*)ei)[EE + i];
    g_dst[i] = d;
    atomicAdd(&g_deg[d], 1);
}

// ---------------- multi-block exclusive scan ----------------
__global__ void scan_phase1() {
    __shared__ int warp_sums[32];
    int tid = threadIdx.x;
    int i = blockIdx.x * SCAN_BLK + tid;
    int v = (i < NN) ? g_deg[i] : 0;
    int lane = tid & 31, wid = tid >> 5;

    int incl = v;
#pragma unroll
    for (int off = 1; off < 32; off <<= 1) {
        int t = __shfl_up_sync(0xffffffffu, incl, off);
        if (lane >= off) incl += t;
    }
    if (lane == 31) warp_sums[wid] = incl;
    __syncthreads();
    if (wid == 0) {
        int ws = warp_sums[lane];
        int wincl = ws;
#pragma unroll
        for (int off = 1; off < 32; off <<= 1) {
            int t = __shfl_up_sync(0xffffffffu, wincl, off);
            if (lane >= off) wincl += t;
        }
        warp_sums[lane] = wincl - ws;
        if (lane == 31) g_blocksum[blockIdx.x] = wincl;
    }
    __syncthreads();
    int excl = incl - v + warp_sums[wid];
    if (i < NN) g_rowptr[i] = excl;
}

__global__ void scan_phase2() {
    __shared__ int ws4[4];
    __shared__ int total;
    int tid = threadIdx.x;            // 128 threads
    int v = (tid < SCAN_NBLK) ? g_blocksum[tid] : 0;
    int lane = tid & 31, wid = tid >> 5;
    int incl = v;
#pragma unroll
    for (int off = 1; off < 32; off <<= 1) {
        int t = __shfl_up_sync(0xffffffffu, incl, off);
        if (lane >= off) incl += t;
    }
    if (lane == 31) ws4[wid] = incl;
    __syncthreads();
    if (tid == 0) {
        int c = 0;
        for (int w = 0; w < 4; w++) { int t = ws4[w]; ws4[w] = c; c += t; }
        total = c;
    }
    __syncthreads();
    if (tid < SCAN_NBLK) g_blocksum[tid] = incl - v + ws4[wid];
    if (tid == 0) g_rowptr[NN] = total;
}

__global__ void scan_phase3() {
    int i = blockIdx.x * SCAN_BLK + threadIdx.x;
    if (i >= NN) return;
    int r = g_rowptr[i] + g_blocksum[blockIdx.x];
    g_rowptr[i] = r;
    g_cursor[i] = r;
}

__global__ void scatter_kernel(const void* __restrict__ ei) {
    int i = blockIdx.x * blockDim.x + threadIdx.x;
    if (i >= EE) return;
    int s;
    if (g_odd_nonzero == 0) s = (int)((const long long*)ei)[i];
    else                    s = ((const int*)ei)[i];
    int d = g_dst[i];
    int pos = atomicAdd(&g_cursor[d], 1);
    g_col[pos] = s;
}

// ---------------- segment max over fp16 shadow: one warp per node ----------------
// Lane owns one half2 (2 features) -> 128B coalesced per edge row.
__global__ void segmax_kernel() {
    int gw   = (blockIdx.x * blockDim.x + threadIdx.x) >> 5;
    int lane = threadIdx.x & 31;
    if (gw >= NN) return;
    int beg = g_rowptr[gw], end = g_rowptr[gw + 1];
    __half2 hacc = __floats2half2_rn(-65504.f, -65504.f);
    for (int base = beg; base < end; base += 32) {
        int cnt = min(32, end - base);
        int s = 0;
        if (lane < cnt) s = g_col[base + lane];
        for (int e = 0; e < cnt; e++) {
            int sv = __shfl_sync(0xffffffffu, s, e);
            unsigned int pv = g_hh[sv * 32 + lane];
            hacc = __hmax2(hacc, *(__half2*)&pv);
        }
    }
    float2 m = __half22float2(hacc);
    if (beg == end) { m.x = 0.f; m.y = 0.f; }
    ((float2*)g_agg)[gw * 32 + lane] = m;
}

// ---------------- 64-wide fp32 GEMM: C = (A [+ A2]) @ W + b ----------------
// Also emits a packed fp16 shadow copy of C for the next layer's gather.
template <bool ADD>
__global__ void gemm64_kernel(const float* __restrict__ A,
                              const float* __restrict__ A2,
                              const float* __restrict__ W,
                              const float* __restrict__ bias,
                              float* __restrict__ Cm,
                              unsigned int* __restrict__ Ch, int n) {
    __shared__ float As[64][68];
    __shared__ float Ws[64][68];
    int tid = threadIdx.x;
    int block_row = blockIdx.x * 64;

    for (int i = tid; i < 1024; i += 256) {
        int k = i >> 4, j4 = i & 15;
        float4 v = ((const float4*)W)[i];
        *(float4*)&Ws[k][j4 * 4] = v;
    }
    for (int i = tid; i < 1024; i += 256) {
        int m = i >> 4, k4 = i & 15;
        int row = block_row + m;
        float4 v = make_float4(0.f, 0.f, 0.f, 0.f);
        if (row < n) {
            v = ((const float4*)A)[row * 16 + k4];
            if (ADD) {
                float4 u = ((const float4*)A2)[row * 16 + k4];
                v.x += u.x; v.y += u.y; v.z += u.z; v.w += u.w;
            }
        }
        *(float4*)&As[m][k4 * 4] = v;
    }
    __syncthreads();

    int tx = tid & 15, ty = tid >> 4;
    int m0 = ty * 4, j0 = tx * 4;
    float acc[4][4];
#pragma unroll
    for (int i = 0; i < 4; i++)
#pragma unroll
        for (int j = 0; j < 4; j++) acc[i][j] = 0.f;

#pragma unroll 16
    for (int k = 0; k < 64; k++) {
        float b0 = Ws[k][j0], b1 = Ws[k][j0 + 1], b2 = Ws[k][j0 + 2], b3 = Ws[k][j0 + 3];
#pragma unroll
        for (int i = 0; i < 4; i++) {
            float a = As[m0 + i][k];
            acc[i][0] = fmaf(a, b0, acc[i][0]);
            acc[i][1] = fmaf(a, b1, acc[i][1]);
            acc[i][2] = fmaf(a, b2, acc[i][2]);
            acc[i][3] = fmaf(a, b3, acc[i][3]);
        }
    }
    float bb0 = bias[j0], bb1 = bias[j0 + 1], bb2 = bias[j0 + 2], bb3 = bias[j0 + 3];
#pragma unroll
    for (int i = 0; i < 4; i++) {
        int row = block_row + m0 + i;
        if (row < n) {
            float4 o = make_float4(acc[i][0] + bb0, acc[i][1] + bb1,
                                   acc[i][2] + bb2, acc[i][3] + bb3);
            ((float4*)Cm)[row * 16 + (j0 >> 2)] = o;
            __half2 p0 = __floats2half2_rn(o.x, o.y);
            __half2 p1 = __floats2half2_rn(o.z, o.w);
            uint2 packed = make_uint2(*(unsigned int*)&p0, *(unsigned int*)&p1);
            ((uint2*)Ch)[row * 16 + (j0 >> 2)] = packed;
        }
    }
}

// ---------------- decoder + log-softmax ----------------
__global__ void decoder_kernel(const float* __restrict__ dw,
                               const float* __restrict__ db,
                               float* __restrict__ out, int n) {
    __shared__ float Ws[HH * CC];
    __shared__ float bs[CC];
    int tid = threadIdx.x;
    for (int i = tid; i < HH * CC; i += blockDim.x) Ws[i] = dw[i];
    if (tid < CC) bs[tid] = db[tid];
    __syncthreads();
    int node = blockIdx.x * blockDim.x + tid;
    if (node >= n) return;
    float acc[CC];
#pragma unroll
    for (int c = 0; c < CC; c++) acc[c] = bs[c];
    const float4* hp = (const float4*)(g_h + node * HH);
#pragma unroll
    for (int k4 = 0; k4 < 16; k4++) {
        float4 v = hp[k4];
        int kb = k4 * 4;
#pragma unroll
        for (int c = 0; c < CC; c++)
            acc[c] += v.x * Ws[(kb + 0) * CC + c] + v.y * Ws[(kb + 1) * CC + c] +
                      v.z * Ws[(kb + 2) * CC + c] + v.w * Ws[(kb + 3) * CC + c];
    }
    float mx = acc[0];
#pragma unroll
    for (int c = 1; c < CC; c++) mx = fmaxf(mx, acc[c]);
    float s = 0.f;
#pragma unroll
    for (int c = 0; c < CC; c++) s += expf(acc[c] - mx);
    float lse = mx + logf(s);
#pragma unroll
    for (int c = 0; c < CC; c++) out[node * CC + c] = acc[c] - lse;
}

// ---------------- launch ----------------
extern "C" void kernel_launch(void* const* d_in, const int* in_sizes, int n_in,
                              void* d_out, int out_size) {
    const float* x      = (const float*)d_in[0];
    const void*  ei     = d_in[1];
    const float* enc_w  = (const float*)d_in[3];
    const float* enc_b  = (const float*)d_in[4];
    const float* proc_w = (const float*)d_in[5];
    const float* proc_b = (const float*)d_in[6];
    const float* dec_w  = (const float*)d_in[7];
    const float* dec_b  = (const float*)d_in[8];
    float* out = (float*)d_out;

    float* hptr = nullptr;
    float* aggptr = nullptr;
    unsigned int* hhptr = nullptr;
    cudaGetSymbolAddress((void**)&hptr, g_h);
    cudaGetSymbolAddress((void**)&aggptr, g_agg);
    cudaGetSymbolAddress((void**)&hhptr, g_hh);

    const int n = NN;

    // CSR build
    zerodetect_kernel<<<(NN + 255) / 256, 256>>>((const unsigned int*)ei);
    convert_kernel<<<(EE + 255) / 256, 256>>>(ei);
    scan_phase1<<<SCAN_NBLK, SCAN_BLK>>>();
    scan_phase2<<<1, 128>>>();
    scan_phase3<<<SCAN_NBLK, SCAN_BLK>>>();
    scatter_kernel<<<(EE + 255) / 256, 256>>>(ei);

    // encoder (emits fp32 h + fp16 shadow)
    gemm64_kernel<false><<<(n + 63) / 64, 256>>>(x, nullptr, enc_w, enc_b,
                                                 hptr, hhptr, n);

    // 6 GIN layers
    for (int it = 0; it < 6; it++) {
        segmax_kernel<<<(NN * 32 + 255) / 256, 256>>>();
        gemm64_kernel<true><<<(n + 63) / 64, 256>>>(hptr, aggptr, proc_w, proc_b,
                                                    hptr, hhptr, n);
    }

    // decoder + log-softmax
    decoder_kernel<<<(n + 127) / 128, 128>>>(dec_w, dec_b, out, n);
}